// round 12
// baseline (speedup 1.0000x reference)
#include <cuda_runtime.h>
#include <cuda_bf16.h>
#include <math.h>

#define H   512
#define E   321
#define CCn 321
#define Tn  96
#define Pn  96
#define Bn  512
#define G4  2048
#define EPB 384
#define NCP 384
#define TB  (Tn*Bn)
#define K3E (3*EPB)        // 1152 = 9*128
#define K3H (3*H)          // 1536 = 12*128
#define NCTAS 128

// dynamic smem layout (per CTA): A two 32KB chunk buffers, W two 16KB
#define SM_A_CHUNK 32768   // 128 rows * 128 k * 2B (two 16KB half-blocks)
#define SM_W_CHUNK 16384   // 64 rows * 128 k * 2B (two 8KB half-blocks)
#define SM_TOTAL   (2*SM_A_CHUNK + 2*SM_W_CHUNK)   // 98304

typedef __nv_bfloat16 bf16;
typedef unsigned int u32;

// ---------------- device globals ------------------------------------------------
__device__ bf16  g_eWih0[(size_t)G4*K3E];
__device__ bf16  g_dWih0[(size_t)G4*K3E];
__device__ bf16  g_eWhh0[(size_t)G4*K3H];
__device__ bf16  g_eWih1[(size_t)G4*K3H];
__device__ bf16  g_eWhh1[(size_t)G4*K3H];
__device__ bf16  g_dWhh0[(size_t)G4*K3H];
__device__ bf16  g_dWih1[(size_t)G4*K3H];
__device__ bf16  g_dWhh1[(size_t)G4*K3H];
__device__ bf16  g_Wfold[(size_t)G4*K3H];
__device__ bf16  g_fcW[(size_t)NCP*K3H];
__device__ bf16  g_fcwt[(size_t)H*K3E];
__device__ bf16  g_dwA[(size_t)G4*K3E];
__device__ bf16  g_x3[(size_t)TB*K3E];
__device__ bf16  g_ys3[(size_t)TB*K3H];
__device__ bf16  g_h[4*(size_t)Bn*K3H];
__device__ bf16  g_i03[(size_t)Bn*K3E];
__device__ float g_pre[(size_t)TB*G4];
__device__ float g_c[2*Bn*H];
__device__ float g_bias[5*G4 + NCP];
__device__ unsigned g_bar[8];

// ---------------- helpers -------------------------------------------------------
__device__ __forceinline__ u32 s2u(const void* p) {
    u32 a; asm("{ .reg .u64 t; cvta.to.shared.u64 t, %1; cvt.u32.u64 %0, t; }" : "=r"(a) : "l"(p)); return a;
}
#define SWZ(o) ((o) ^ (((o) >> 3) & 0x70))
__device__ __forceinline__ float sigmf(float x) { return 1.f / (1.f + __expf(-x)); }
__device__ __forceinline__ void split2(float x, bf16& h, bf16& l) {
    h = __float2bfloat16(x);
    l = __float2bfloat16(x - __bfloat162float(h));
}
__device__ __forceinline__ void ldm4(u32& r0, u32& r1, u32& r2, u32& r3, u32 a) {
    asm volatile("ldmatrix.sync.aligned.m8n8.x4.shared.b16 {%0,%1,%2,%3}, [%4];"
                 : "=r"(r0), "=r"(r1), "=r"(r2), "=r"(r3) : "r"(a));
}
__device__ __forceinline__ void mma16816(float* c, u32 a0, u32 a1, u32 a2, u32 a3, u32 b0, u32 b1) {
    asm volatile(
        "mma.sync.aligned.m16n8k16.row.col.f32.bf16.bf16.f32 "
        "{%0,%1,%2,%3}, {%4,%5,%6,%7}, {%8,%9}, {%0,%1,%2,%3};"
        : "+f"(c[0]), "+f"(c[1]), "+f"(c[2]), "+f"(c[3])
        : "r"(a0), "r"(a1), "r"(a2), "r"(a3), "r"(b0), "r"(b1));
}

// ---------------- grid barrier (128 CTAs co-resident on 148 SMs) ----------------
__device__ __forceinline__ void gridbar(unsigned* cnt, volatile unsigned* rel, unsigned& phase)
{
    __syncthreads();
    if (threadIdx.x == 0) {
        __threadfence();
        const unsigned target = phase + 1u;
        const unsigned v = atomicAdd(cnt, 1u);
        if (v == target * (unsigned)NCTAS - 1u) {
            __threadfence();
            *rel = target;
        } else {
            while (*rel < target) { __nanosleep(32); }
        }
    }
    __syncthreads();
    __threadfence();
    phase += 1u;
}

// ---------------- GEMM body: 128x64 tile, 256 thr, K-chunk=128, frag pipeline ---
// Each chunk is stored as two 128-byte-row half-blocks (k 0-63 | k 64-127).
__device__ __forceinline__ void gemm_body(
    char* As0, char* As1, char* Ws0, char* Ws1,
    const bf16* A1, int lda1, const bf16* W1, int ldw1, int nc1,
    const bf16* A2, int lda2, const bf16* W2, int ldw2, int nc2,
    int bm, int bn, float acc[2][4][4])
{
    const int tid = threadIdx.x;
    const int warp = tid >> 5, lane = tid & 31;
    const int wm = warp & 3, wn = warp >> 2;
    // A loader: 2 thr/row, each loads one 64-elem k-half (128 B = 8 uint4)
    const int la_row = tid >> 1, la_half = tid & 1;
    // W loader: 4 thr/row, quarter q: half=q>>1, 32-elem sub (64 B = 4 uint4)
    const int lw_row = tid >> 2, lw_q = tid & 3;
    const int lw_half = lw_q >> 1, lw_sub = (lw_q & 1);
    const int a_r = wm * 32 + (lane & 15), a_kb = (lane >> 4) * 16;
    const int b_r = wn * 32 + ((lane >> 4) << 3) + (lane & 7), b_kb = ((lane >> 3) & 1) * 16;
    const u32 sA0 = s2u(As0), sA1v = s2u(As1), sW0 = s2u(Ws0), sW1v = s2u(Ws1);
    const int tot = nc1 + nc2;

    // prologue: chunk 0 -> buf 0
    {
        const bf16 *Ag, *Wg; int lda, ldw;
        if (0 < nc1) { Ag = A1; Wg = W1; lda = lda1; ldw = ldw1; }
        else         { Ag = A2; Wg = W2; lda = lda2; ldw = ldw2; }
        const bf16* ap = Ag + (size_t)(bm + la_row) * lda + la_half * 64;
        char* ad = As0 + la_half * 16384;
#pragma unroll
        for (int j = 0; j < 8; ++j)
            *(uint4*)(ad + SWZ(la_row * 128 + j * 16)) = *(const uint4*)(ap + j * 8);
        const bf16* wp = Wg + (size_t)(bn + lw_row) * ldw + lw_half * 64 + lw_sub * 32;
        char* wd = Ws0 + lw_half * 8192;
#pragma unroll
        for (int j = 0; j < 4; ++j)
            *(uint4*)(wd + SWZ(lw_row * 128 + lw_sub * 64 + j * 16)) = *(const uint4*)(wp + j * 8);
    }
    __syncthreads();

    int buf = 0;
    uint4 pa[8], pw[4];
    for (int i = 0; i < tot; ++i) {
        const bool more = (i + 1 < tot);
        if (more) {
            const bf16 *Ag, *Wg; int lda, ldw, k0;
            if (i + 1 < nc1) { Ag = A1; Wg = W1; lda = lda1; ldw = ldw1; k0 = (i + 1) * 128; }
            else             { Ag = A2; Wg = W2; lda = lda2; ldw = ldw2; k0 = (i + 1 - nc1) * 128; }
            const bf16* ap = Ag + (size_t)(bm + la_row) * lda + k0 + la_half * 64;
#pragma unroll
            for (int j = 0; j < 8; ++j) pa[j] = *(const uint4*)(ap + j * 8);
            const bf16* wp = Wg + (size_t)(bn + lw_row) * ldw + k0 + lw_half * 64 + lw_sub * 32;
#pragma unroll
            for (int j = 0; j < 4; ++j) pw[j] = *(const uint4*)(wp + j * 8);
        }
        const u32 sAc = buf ? sA1v : sA0;
        const u32 sWc = buf ? sW1v : sW0;

        // fragment-pipelined inner loop: 8 sub-k groups of 16 elems
        u32 fa[2][8], fb[2][8];
        ldm4(fa[0][0], fa[0][1], fa[0][2], fa[0][3], sAc + SWZ(a_r * 128 + a_kb));
        ldm4(fa[0][4], fa[0][5], fa[0][6], fa[0][7], sAc + SWZ((a_r + 16) * 128 + a_kb));
        ldm4(fb[0][0], fb[0][1], fb[0][2], fb[0][3], sWc + SWZ(b_r * 128 + b_kb));
        ldm4(fb[0][4], fb[0][5], fb[0][6], fb[0][7], sWc + SWZ((b_r + 16) * 128 + b_kb));
#pragma unroll
        for (int kk = 0; kk < 8; ++kk) {
            const int cur = kk & 1, nxt = cur ^ 1;
            if (kk < 7) {
                const int kb = (kk + 1) * 32;
                const u32 aoff = (kb >> 7) ? 16384u : 0u;
                const u32 woff = (kb >> 7) ? 8192u : 0u;
                const int lkb = kb & 127;
                ldm4(fa[nxt][0], fa[nxt][1], fa[nxt][2], fa[nxt][3], sAc + aoff + SWZ(a_r * 128 + lkb + a_kb));
                ldm4(fa[nxt][4], fa[nxt][5], fa[nxt][6], fa[nxt][7], sAc + aoff + SWZ((a_r + 16) * 128 + lkb + a_kb));
                ldm4(fb[nxt][0], fb[nxt][1], fb[nxt][2], fb[nxt][3], sWc + woff + SWZ(b_r * 128 + lkb + b_kb));
                ldm4(fb[nxt][4], fb[nxt][5], fb[nxt][6], fb[nxt][7], sWc + woff + SWZ((b_r + 16) * 128 + lkb + b_kb));
            }
            mma16816(acc[0][0], fa[cur][0], fa[cur][1], fa[cur][2], fa[cur][3], fb[cur][0], fb[cur][1]);
            mma16816(acc[0][1], fa[cur][0], fa[cur][1], fa[cur][2], fa[cur][3], fb[cur][2], fb[cur][3]);
            mma16816(acc[0][2], fa[cur][0], fa[cur][1], fa[cur][2], fa[cur][3], fb[cur][4], fb[cur][5]);
            mma16816(acc[0][3], fa[cur][0], fa[cur][1], fa[cur][2], fa[cur][3], fb[cur][6], fb[cur][7]);
            mma16816(acc[1][0], fa[cur][4], fa[cur][5], fa[cur][6], fa[cur][7], fb[cur][0], fb[cur][1]);
            mma16816(acc[1][1], fa[cur][4], fa[cur][5], fa[cur][6], fa[cur][7], fb[cur][2], fb[cur][3]);
            mma16816(acc[1][2], fa[cur][4], fa[cur][5], fa[cur][6], fa[cur][7], fb[cur][4], fb[cur][5]);
            mma16816(acc[1][3], fa[cur][4], fa[cur][5], fa[cur][6], fa[cur][7], fb[cur][6], fb[cur][7]);
        }

        if (more) {
            char* Asn = buf ? As0 : As1;
            char* Wsn = buf ? Ws0 : Ws1;
            char* ad = Asn + la_half * 16384;
#pragma unroll
            for (int j = 0; j < 8; ++j)
                *(uint4*)(ad + SWZ(la_row * 128 + j * 16)) = pa[j];
            char* wd = Wsn + lw_half * 8192;
#pragma unroll
            for (int j = 0; j < 4; ++j)
                *(uint4*)(wd + SWZ(lw_row * 128 + lw_sub * 64 + j * 16)) = pw[j];
            __syncthreads();
            buf ^= 1;
        }
    }
}

// ---------------- fused LSTM epilogue (with optional pre) -----------------------
__device__ __forceinline__ void lstm_epi(
    float acc[2][4][4], int bm, int bn,
    const float* bias, const float* pre,
    float* cst, bf16* hout, bf16* ysout)
{
    const int tid = threadIdx.x;
    const int warp = tid >> 5, lane = tid & 31;
    const int wm = warp & 3, wn = warp >> 2;
    const int rbase = bm + wm * 32 + (lane >> 2);
#pragma unroll
    for (int mt = 0; mt < 2; ++mt) {
#pragma unroll
        for (int nt = 0; nt < 4; ++nt) {
            float i1 = acc[mt][nt][0], f1 = acc[mt][nt][1];
            float i2 = acc[mt][nt][2], f2 = acc[mt][nt][3];
            const float gg1 = __shfl_xor_sync(0xffffffffu, i1, 1);
            const float oo1 = __shfl_xor_sync(0xffffffffu, f1, 1);
            const float gg2 = __shfl_xor_sync(0xffffffffu, i2, 1);
            const float oo2 = __shfl_xor_sync(0xffffffffu, f2, 1);
            if ((lane & 1) == 0) {
                const int col = bn + wn * 32 + nt * 8 + 2 * (lane & 3);
                const int jh = col >> 2;
                const float4 b4 = *(const float4*)&bias[col];
                const int r1 = rbase + mt * 16, r2 = r1 + 8;
                float gi1 = i1 + b4.x, gf1 = f1 + b4.y, gG1 = gg1 + b4.z, go1 = oo1 + b4.w;
                float gi2 = i2 + b4.x, gf2 = f2 + b4.y, gG2 = gg2 + b4.z, go2 = oo2 + b4.w;
                if (pre) {
                    const float4 p1 = *(const float4*)&pre[(size_t)r1 * G4 + col];
                    const float4 p2 = *(const float4*)&pre[(size_t)r2 * G4 + col];
                    gi1 += p1.x; gf1 += p1.y; gG1 += p1.z; go1 += p1.w;
                    gi2 += p2.x; gf2 += p2.y; gG2 += p2.z; go2 += p2.w;
                }
                {
                    const size_t ci = (size_t)r1 * H + jh;
                    const float cv = sigmf(gf1) * cst[ci] + sigmf(gi1) * tanhf(gG1);
                    const float hv = sigmf(go1) * tanhf(cv);
                    cst[ci] = cv;
                    bf16 hh, hl; split2(hv, hh, hl);
                    bf16* hr = hout + (size_t)r1 * K3H;
                    hr[jh] = hh; hr[H + jh] = hh; hr[2 * H + jh] = hl;
                    if (ysout) { bf16* yr = ysout + (size_t)r1 * K3H; yr[jh] = hh; yr[H + jh] = hh; yr[2 * H + jh] = hl; }
                }
                {
                    const size_t ci = (size_t)r2 * H + jh;
                    const float cv = sigmf(gf2) * cst[ci] + sigmf(gi2) * tanhf(gG2);
                    const float hv = sigmf(go2) * tanhf(cv);
                    cst[ci] = cv;
                    bf16 hh, hl; split2(hv, hh, hl);
                    bf16* hr = hout + (size_t)r2 * K3H;
                    hr[jh] = hh; hr[H + jh] = hh; hr[2 * H + jh] = hl;
                    if (ysout) { bf16* yr = ysout + (size_t)r2 * K3H; yr[jh] = hh; yr[H + jh] = hh; yr[2 * H + jh] = hl; }
                }
            }
        }
    }
}

// ---------------- batched GEMM (EPI=0 plain fp32 out, EPI=2 fc scatter) ---------
template<int EPI>
__global__ __launch_bounds__(256)
void hgemm(const bf16* __restrict__ A1, int lda1,
           const bf16* __restrict__ W1, int ldw1, int nc1,
           const float* __restrict__ bias,
           float* __restrict__ Cout, int ldc)
{
    extern __shared__ char sm[];
    char* As0 = sm;
    char* As1 = sm + SM_A_CHUNK;
    char* Ws0 = sm + 2 * SM_A_CHUNK;
    char* Ws1 = sm + 2 * SM_A_CHUNK + SM_W_CHUNK;
    const int bm = blockIdx.y * 128, bn = blockIdx.x * 64;
    float acc[2][4][4];
#pragma unroll
    for (int m = 0; m < 2; ++m)
#pragma unroll
        for (int n = 0; n < 4; ++n)
#pragma unroll
            for (int q = 0; q < 4; ++q) acc[m][n][q] = 0.f;

    gemm_body(As0, As1, Ws0, Ws1,
              A1, lda1, W1, ldw1, nc1,
              (const bf16*)0, 0, (const bf16*)0, 0, 0, bm, bn, acc);

    const int tid = threadIdx.x;
    const int warp = tid >> 5, lane = tid & 31;
    const int wm = warp & 3, wn = warp >> 2;
    const int rbase = bm + wm * 32 + (lane >> 2);

    if (EPI == 0) {
#pragma unroll
        for (int mt = 0; mt < 2; ++mt) {
#pragma unroll
            for (int nt = 0; nt < 4; ++nt) {
                const int col = bn + wn * 32 + nt * 8 + 2 * (lane & 3);
                const int r1 = rbase + mt * 16, r2 = r1 + 8;
                *(float2*)&Cout[(size_t)r1 * ldc + col] = make_float2(acc[mt][nt][0], acc[mt][nt][1]);
                *(float2*)&Cout[(size_t)r2 * ldc + col] = make_float2(acc[mt][nt][2], acc[mt][nt][3]);
            }
        }
    } else {
#pragma unroll
        for (int mt = 0; mt < 2; ++mt) {
#pragma unroll
            for (int nt = 0; nt < 4; ++nt) {
                const int col = bn + wn * 32 + nt * 8 + 2 * (lane & 3);
                const int r1 = rbase + mt * 16, r2 = r1 + 8;
                {
                    const int bb = r1 & (Bn - 1), tt = r1 >> 9;
                    float* o = Cout + (size_t)bb * (Pn * CCn) + (size_t)tt * CCn;
                    if (col < CCn)     o[col]     = acc[mt][nt][0] + bias[col];
                    if (col + 1 < CCn) o[col + 1] = acc[mt][nt][1] + bias[col + 1];
                }
                {
                    const int bb = r2 & (Bn - 1), tt = r2 >> 9;
                    float* o = Cout + (size_t)bb * (Pn * CCn) + (size_t)tt * CCn;
                    if (col < CCn)     o[col]     = acc[mt][nt][2] + bias[col];
                    if (col + 1 < CCn) o[col + 1] = acc[mt][nt][3] + bias[col + 1];
                }
            }
        }
    }
}

// ---------------- persistent encoder-layer recurrence ---------------------------
__global__ __launch_bounds__(256)
void enc_seq(bf16* hA, bf16* hBp, const bf16* __restrict__ W,
             const float* __restrict__ bias, const float* __restrict__ preBase,
             float* __restrict__ cst, bf16* __restrict__ ysBase, int steps,
             unsigned* barCnt, unsigned* barRel)
{
    extern __shared__ char sm[];
    char* As0 = sm;
    char* As1 = sm + SM_A_CHUNK;
    char* Ws0 = sm + 2 * SM_A_CHUNK;
    char* Ws1 = sm + 2 * SM_A_CHUNK + SM_W_CHUNK;
    const int bm = blockIdx.y * 128, bn = blockIdx.x * 64;
    bf16* hc = hA; bf16* hn = hBp;
    unsigned phase = 0;
    for (int t = 0; t < steps; ++t) {
        float acc[2][4][4];
#pragma unroll
        for (int m = 0; m < 2; ++m)
#pragma unroll
            for (int n = 0; n < 4; ++n)
#pragma unroll
                for (int q = 0; q < 4; ++q) acc[m][n][q] = 0.f;
        gemm_body(As0, As1, Ws0, Ws1,
                  hc, K3H, W, K3H, K3H / 128,
                  (const bf16*)0, 0, (const bf16*)0, 0, 0, bm, bn, acc);
        lstm_epi(acc, bm, bn, bias, preBase + (size_t)t * Bn * G4, cst, hn,
                 ysBase ? (ysBase + (size_t)t * Bn * K3H) : (bf16*)0);
        gridbar(barCnt, (volatile unsigned*)barRel, phase);
        bf16* tmp = hc; hc = hn; hn = tmp;
    }
}

// ---------------- persistent decoder recurrence ---------------------------------
__global__ __launch_bounds__(256)
void dec_seq(bf16* h0A, bf16* h0B, bf16* h1A, bf16* h1B,
             const bf16* __restrict__ i03,
             const bf16* __restrict__ dWih0, const bf16* __restrict__ Wfold,
             const bf16* __restrict__ dWhh0, const bf16* __restrict__ dWih1,
             const bf16* __restrict__ dWhh1,
             const float* __restrict__ dB0, const float* __restrict__ dB0f,
             const float* __restrict__ dB1,
             float* __restrict__ c0, float* __restrict__ c1,
             bf16* __restrict__ ysBase, int steps,
             unsigned* barCnt, unsigned* barRel)
{
    extern __shared__ char sm[];
    char* As0 = sm;
    char* As1 = sm + SM_A_CHUNK;
    char* Ws0 = sm + 2 * SM_A_CHUNK;
    char* Ws1 = sm + 2 * SM_A_CHUNK + SM_W_CHUNK;
    const int bm = blockIdx.y * 128, bn = blockIdx.x * 64;
    bf16 *h0c = h0A, *h0n = h0B, *h1c = h1A, *h1n = h1B;
    unsigned phase = 0;
    for (int t = 0; t < steps; ++t) {
        {
            float acc[2][4][4];
#pragma unroll
            for (int m = 0; m < 2; ++m)
#pragma unroll
                for (int n = 0; n < 4; ++n)
#pragma unroll
                    for (int q = 0; q < 4; ++q) acc[m][n][q] = 0.f;
            if (t == 0) {
                gemm_body(As0, As1, Ws0, Ws1,
                          i03, K3E, dWih0, K3E, K3E / 128,
                          h0c, K3H, dWhh0, K3H, K3H / 128, bm, bn, acc);
                lstm_epi(acc, bm, bn, dB0, (const float*)0, c0, h0n, (bf16*)0);
            } else {
                gemm_body(As0, As1, Ws0, Ws1,
                          h1c, K3H, Wfold, K3H, K3H / 128,
                          h0c, K3H, dWhh0, K3H, K3H / 128, bm, bn, acc);
                lstm_epi(acc, bm, bn, dB0f, (const float*)0, c0, h0n, (bf16*)0);
            }
            gridbar(barCnt, (volatile unsigned*)barRel, phase);
            bf16* tmp = h0c; h0c = h0n; h0n = tmp;
        }
        {
            float acc[2][4][4];
#pragma unroll
            for (int m = 0; m < 2; ++m)
#pragma unroll
                for (int n = 0; n < 4; ++n)
#pragma unroll
                    for (int q = 0; q < 4; ++q) acc[m][n][q] = 0.f;
            gemm_body(As0, As1, Ws0, Ws1,
                      h0c, K3H, dWih1, K3H, K3H / 128,
                      h1c, K3H, dWhh1, K3H, K3H / 128, bm, bn, acc);
            lstm_epi(acc, bm, bn, dB1, (const float*)0, c1, h1n,
                     ysBase + (size_t)t * Bn * K3H);
            gridbar(barCnt, (volatile unsigned*)barRel, phase);
            bf16* tmp = h1c; h1c = h1n; h1n = tmp;
        }
    }
}

// ---------------- setup kernels ---------------------------------------------------
__global__ void k_w3(const float* __restrict__ src, bf16* __restrict__ dst, int K, int Kp)
{
    size_t idx = (size_t)blockIdx.x * blockDim.x + threadIdx.x;
    if (idx >= (size_t)G4 * Kp) return;
    int np = (int)(idx / Kp), k = (int)(idx % Kp);
    int j = np >> 2, g = np & 3;
    float v = (k < K) ? src[((size_t)(g * H + j)) * K + k] : 0.f;
    bf16 h, l; split2(v, h, l);
    bf16* d = dst + (size_t)np * 3 * Kp;
    d[k] = h; d[Kp + k] = l; d[2 * Kp + k] = h;
}
__global__ void k_a3w(const float* __restrict__ src, bf16* __restrict__ dst, int K, int Kp)
{
    size_t idx = (size_t)blockIdx.x * blockDim.x + threadIdx.x;
    if (idx >= (size_t)G4 * Kp) return;
    int np = (int)(idx / Kp), k = (int)(idx % Kp);
    int j = np >> 2, g = np & 3;
    float v = (k < K) ? src[((size_t)(g * H + j)) * K + k] : 0.f;
    bf16 h, l; split2(v, h, l);
    bf16* d = dst + (size_t)np * 3 * Kp;
    d[k] = h; d[Kp + k] = h; d[2 * Kp + k] = l;
}
__global__ void k_fcwt3(const float* __restrict__ fcW, bf16* __restrict__ dst)
{
    int idx = blockIdx.x * blockDim.x + threadIdx.x;
    if (idx >= H * EPB) return;
    int hrow = idx / EPB, c = idx % EPB;
    float v = (c < CCn) ? fcW[(size_t)c * H + hrow] : 0.f;
    bf16 h, l; split2(v, h, l);
    bf16* d = dst + (size_t)hrow * K3E;
    d[c] = h; d[EPB + c] = l; d[2 * EPB + c] = h;
}
__global__ void k_fcw3(const float* __restrict__ fcW, bf16* __restrict__ dst)
{
    int idx = blockIdx.x * blockDim.x + threadIdx.x;
    if (idx >= NCP * H) return;
    int n = idx / H, hcol = idx % H;
    float v = (n < CCn) ? fcW[(size_t)n * H + hcol] : 0.f;
    bf16 h, l; split2(v, h, l);
    bf16* d = dst + (size_t)n * K3H;
    d[hcol] = h; d[H + hcol] = l; d[2 * H + hcol] = h;
}
__global__ void k_split3w(const float* __restrict__ src, bf16* __restrict__ dst)
{
    size_t idx = (size_t)blockIdx.x * blockDim.x + threadIdx.x;
    if (idx >= (size_t)G4 * H) return;
    int np = (int)(idx / H), k = (int)(idx % H);
    bf16 h, l; split2(src[idx], h, l);
    bf16* d = dst + (size_t)np * K3H;
    d[k] = h; d[H + k] = l; d[2 * H + k] = h;
}
__global__ void k_x3(const float* __restrict__ x, bf16* __restrict__ dst)
{
    size_t idx = (size_t)blockIdx.x * blockDim.x + threadIdx.x;
    if (idx >= (size_t)TB * EPB) return;
    int e = (int)(idx % EPB);
    int b = (int)((idx / EPB) % Bn);
    int t = (int)(idx / ((size_t)EPB * Bn));
    float v = (e < E) ? x[(size_t)b * Tn * E + (size_t)t * E + e] : 0.f;
    bf16 h, l; split2(v, h, l);
    bf16* d = dst + ((size_t)t * Bn + b) * K3E;
    d[e] = h; d[EPB + e] = h; d[2 * EPB + e] = l;
}
__global__ void k_i03(const float* __restrict__ x, bf16* __restrict__ dst)
{
    int i = blockIdx.x * blockDim.x + threadIdx.x;
    if (i >= Bn * EPB) return;
    int b = i / EPB, e = i % EPB;
    float v = (e < E) ? x[(size_t)b * Tn * E + (size_t)(Tn - 1) * E + e] : 0.f;
    bf16 h, l; split2(v, h, l);
    bf16* d = dst + (size_t)b * K3E;
    d[e] = h; d[EPB + e] = h; d[2 * EPB + e] = l;
}
__global__ void k_bias(const float* __restrict__ a, const float* __restrict__ b, float* __restrict__ d)
{
    int n = blockIdx.x * blockDim.x + threadIdx.x;
    if (n >= G4) return;
    int j = n >> 2, g = n & 3;
    d[n] = a[g * H + j] + b[g * H + j];
}
__global__ void k_foldbias(const float* __restrict__ dWih0, const float* __restrict__ fcb,
                           const float* __restrict__ dB0, float* __restrict__ out)
{
    int n = blockIdx.x * blockDim.x + threadIdx.x;
    if (n >= G4) return;
    int j = n >> 2, g = n & 3;
    float s = dB0[n];
    const float* row = dWih0 + (size_t)(g * H + j) * E;
    for (int c = 0; c < CCn; ++c) s += row[c] * fcb[c];
    out[n] = s;
}
__global__ void k_fcb(const float* __restrict__ fcb, float* __restrict__ d)
{
    int n = blockIdx.x * blockDim.x + threadIdx.x;
    if (n >= NCP) return;
    d[n] = (n < CCn) ? fcb[n] : 0.f;
}
__global__ void k_zf(float* p, int n) { int i = blockIdx.x * blockDim.x + threadIdx.x; if (i < n) p[i] = 0.f; }
__global__ void k_zb(bf16* p, size_t n) { size_t i = (size_t)blockIdx.x * blockDim.x + threadIdx.x; if (i < n) ((unsigned short*)p)[i] = 0; }
__global__ void k_zu(unsigned* p) { if (threadIdx.x < 8) p[threadIdx.x] = 0u; }

// ---------------- entry ----------------------------------------------------------
extern "C" void kernel_launch(void* const* d_in, const int* in_sizes, int n_in,
                              void* d_out, int out_size)
{
    const float* x_enc  = (const float*)d_in[0];
    const float* e_Wih0 = (const float*)d_in[4],  *e_Whh0 = (const float*)d_in[5];
    const float* e_bih0 = (const float*)d_in[6],  *e_bhh0 = (const float*)d_in[7];
    const float* e_Wih1 = (const float*)d_in[8],  *e_Whh1 = (const float*)d_in[9];
    const float* e_bih1 = (const float*)d_in[10], *e_bhh1 = (const float*)d_in[11];
    const float* d_Wih0 = (const float*)d_in[12], *d_Whh0 = (const float*)d_in[13];
    const float* d_bih0 = (const float*)d_in[14], *d_bhh0 = (const float*)d_in[15];
    const float* d_Wih1 = (const float*)d_in[16], *d_Whh1 = (const float*)d_in[17];
    const float* d_bih1 = (const float*)d_in[18], *d_bhh1 = (const float*)d_in[19];
    const float* fc_W   = (const float*)d_in[20], *fc_b   = (const float*)d_in[21];
    float* out = (float*)d_out;

    bf16 *eWih0, *dWih0, *eWhh0, *eWih1, *eWhh1, *dWhh0, *dWih1, *dWhh1;
    bf16 *Wfold, *fcW3, *fcwt, *dwA, *x3, *ys3, *hB, *i03;
    float *pre, *cbuf, *bias;
    unsigned* bar;
    cudaGetSymbolAddress((void**)&eWih0, g_eWih0); cudaGetSymbolAddress((void**)&dWih0, g_dWih0);
    cudaGetSymbolAddress((void**)&eWhh0, g_eWhh0); cudaGetSymbolAddress((void**)&eWih1, g_eWih1);
    cudaGetSymbolAddress((void**)&eWhh1, g_eWhh1); cudaGetSymbolAddress((void**)&dWhh0, g_dWhh0);
    cudaGetSymbolAddress((void**)&dWih1, g_dWih1); cudaGetSymbolAddress((void**)&dWhh1, g_dWhh1);
    cudaGetSymbolAddress((void**)&Wfold, g_Wfold); cudaGetSymbolAddress((void**)&fcW3,  g_fcW);
    cudaGetSymbolAddress((void**)&fcwt,  g_fcwt);  cudaGetSymbolAddress((void**)&dwA,   g_dwA);
    cudaGetSymbolAddress((void**)&x3,    g_x3);    cudaGetSymbolAddress((void**)&ys3,   g_ys3);
    cudaGetSymbolAddress((void**)&hB,    g_h);     cudaGetSymbolAddress((void**)&i03,   g_i03);
    cudaGetSymbolAddress((void**)&pre,   g_pre);   cudaGetSymbolAddress((void**)&cbuf,  g_c);
    cudaGetSymbolAddress((void**)&bias,  g_bias);  cudaGetSymbolAddress((void**)&bar,   g_bar);

    cudaFuncSetAttribute(hgemm<0>, cudaFuncAttributeMaxDynamicSharedMemorySize, SM_TOTAL);
    cudaFuncSetAttribute(hgemm<2>, cudaFuncAttributeMaxDynamicSharedMemorySize, SM_TOTAL);
    cudaFuncSetAttribute(enc_seq,  cudaFuncAttributeMaxDynamicSharedMemorySize, SM_TOTAL);
    cudaFuncSetAttribute(dec_seq,  cudaFuncAttributeMaxDynamicSharedMemorySize, SM_TOTAL);

    float* eB0  = bias;          float* eB1 = bias + G4;
    float* dB0  = bias + 2 * G4; float* dB1 = bias + 3 * G4;
    float* dB0f = bias + 4 * G4; float* fcb = bias + 5 * G4;
    const size_t HP = (size_t)Bn * K3H;
    bf16* h0A = hB;          bf16* h0B = hB + HP;
    bf16* h1A = hB + 2 * HP; bf16* h1B = hB + 3 * HP;
    float* c0 = cbuf; float* c1 = cbuf + (size_t)Bn * H;
    const int thr = 256;
    const size_t BHK = (size_t)Bn * K3H;

    // ---- setup ----
    {
        size_t nE = (size_t)G4 * EPB, nH = (size_t)G4 * H;
        k_w3<<<(unsigned)((nE + thr - 1) / thr), thr>>>(e_Wih0, eWih0, E, EPB);
        k_w3<<<(unsigned)((nE + thr - 1) / thr), thr>>>(d_Wih0, dWih0, E, EPB);
        k_w3<<<(unsigned)((nH + thr - 1) / thr), thr>>>(e_Whh0, eWhh0, H, H);
        k_w3<<<(unsigned)((nH + thr - 1) / thr), thr>>>(e_Wih1, eWih1, H, H);
        k_w3<<<(unsigned)((nH + thr - 1) / thr), thr>>>(e_Whh1, eWhh1, H, H);
        k_w3<<<(unsigned)((nH + thr - 1) / thr), thr>>>(d_Whh0, dWhh0, H, H);
        k_w3<<<(unsigned)((nH + thr - 1) / thr), thr>>>(d_Wih1, dWih1, H, H);
        k_w3<<<(unsigned)((nH + thr - 1) / thr), thr>>>(d_Whh1, dWhh1, H, H);
        k_a3w<<<(unsigned)((nE + thr - 1) / thr), thr>>>(d_Wih0, dwA, E, EPB);
        k_fcwt3<<<(H * EPB + thr - 1) / thr, thr>>>(fc_W, fcwt);
        k_fcw3<<<(NCP * H + thr - 1) / thr, thr>>>(fc_W, fcW3);
        k_bias<<<(G4 + thr - 1) / thr, thr>>>(e_bih0, e_bhh0, eB0);
        k_bias<<<(G4 + thr - 1) / thr, thr>>>(e_bih1, e_bhh1, eB1);
        k_bias<<<(G4 + thr - 1) / thr, thr>>>(d_bih0, d_bhh0, dB0);
        k_bias<<<(G4 + thr - 1) / thr, thr>>>(d_bih1, d_bhh1, dB1);
        k_foldbias<<<(G4 + thr - 1) / thr, thr>>>(d_Wih0, fc_b, dB0, dB0f);
        k_fcb<<<(NCP + thr - 1) / thr, thr>>>(fc_b, fcb);
        k_zu<<<1, 32>>>(bar);
    }
    // Wfold = dWih0' @ fcW^T (fp32) then split3 W-style
    {
        dim3 g(H / 64, G4 / 128);
        hgemm<0><<<g, 256, SM_TOTAL>>>(dwA, K3E, fcwt, K3E, K3E / 128, (const float*)0, pre, H);
        size_t n = (size_t)G4 * H;
        k_split3w<<<(unsigned)((n + thr - 1) / thr), thr>>>(pre, Wfold);
    }
    // ---- states + inputs ----
    k_zf<<<(2 * Bn * H + thr - 1) / thr, thr>>>(cbuf, 2 * Bn * H);
    k_zb<<<(unsigned)((4 * BHK + thr - 1) / thr), thr>>>(hB, 4 * BHK);
    {
        size_t n = (size_t)TB * EPB;
        k_x3<<<(unsigned)((n + thr - 1) / thr), thr>>>(x_enc, x3);
    }
    k_i03<<<(Bn * EPB + thr - 1) / thr, thr>>>(x_enc, i03);

    // ---- encoder L0: batched input GEMM, then persistent recurrence ----
    {
        dim3 g(G4 / 64, TB / 128);
        hgemm<0><<<g, 256, SM_TOTAL>>>(x3, K3E, eWih0, K3E, K3E / 128, (const float*)0, pre, G4);
    }
    {
        dim3 g(G4 / 64, Bn / 128);  // 32 x 4 = 128 CTAs
        enc_seq<<<g, 256, SM_TOTAL>>>(h0A, h0B, eWhh0, eB0, pre, c0, ys3, Tn, bar + 0, bar + 1);
    }
    // ---- encoder L1 ----
    {
        dim3 g(G4 / 64, TB / 128);
        hgemm<0><<<g, 256, SM_TOTAL>>>(ys3, K3H, eWih1, K3H, K3H / 128, (const float*)0, pre, G4);
    }
    {
        dim3 g(G4 / 64, Bn / 128);
        enc_seq<<<g, 256, SM_TOTAL>>>(h1A, h1B, eWhh1, eB1, pre, c1, (bf16*)0, Tn, bar + 2, bar + 3);
    }
    // ---- decoder (persistent, fc folded) ----
    {
        dim3 g(G4 / 64, Bn / 128);
        dec_seq<<<g, 256, SM_TOTAL>>>(h0A, h0B, h1A, h1B, i03,
                                      dWih0, Wfold, dWhh0, dWih1, dWhh1,
                                      dB0, dB0f, dB1, c0, c1, ys3, Pn, bar + 4, bar + 5);
    }
    // ---- batched final fc ----
    {
        dim3 g(NCP / 64, TB / 128);
        hgemm<2><<<g, 256, SM_TOTAL>>>(ys3, K3H, fcW3, K3H, K3H / 128, fcb, out, 0);
    }
}

// round 13
// speedup vs baseline: 1.5558x; 1.5558x over previous
#include <cuda_runtime.h>
#include <cuda_bf16.h>
#include <math.h>

#define H   512
#define E   321
#define CCn 321
#define Tn  96
#define Pn  96
#define Bn  512
#define G4  2048
#define EPB 384
#define NCP 384
#define TB  (Tn*Bn)
#define K3E (3*EPB)        // 1152
#define K3H (3*H)          // 1536
#define NCTAS 128

typedef __nv_bfloat16 bf16;
typedef unsigned int u32;

// ---------------- device globals ------------------------------------------------
__device__ bf16  g_eWih0[(size_t)G4*K3E];
__device__ bf16  g_dWih0[(size_t)G4*K3E];
__device__ bf16  g_eWhh0[(size_t)G4*K3H];
__device__ bf16  g_eWih1[(size_t)G4*K3H];
__device__ bf16  g_eWhh1[(size_t)G4*K3H];
__device__ bf16  g_dWhh0[(size_t)G4*K3H];
__device__ bf16  g_dWih1[(size_t)G4*K3H];
__device__ bf16  g_dWhh1[(size_t)G4*K3H];
__device__ bf16  g_Wfold[(size_t)G4*K3H];
__device__ bf16  g_fcW[(size_t)NCP*K3H];
__device__ bf16  g_fcwt[(size_t)H*K3E];
__device__ bf16  g_dwA[(size_t)G4*K3E];
__device__ bf16  g_x3[(size_t)TB*K3E];
__device__ bf16  g_ys3[(size_t)TB*K3H];
__device__ bf16  g_h[4*(size_t)Bn*K3H];
__device__ bf16  g_i03[(size_t)Bn*K3E];
__device__ float g_pre[(size_t)TB*G4];
__device__ float g_c[2*Bn*H];
__device__ float g_bias[5*G4 + NCP];
__device__ unsigned g_bar[8];

// ---------------- helpers -------------------------------------------------------
__device__ __forceinline__ u32 s2u(const void* p) {
    u32 a; asm("{ .reg .u64 t; cvta.to.shared.u64 t, %1; cvt.u32.u64 %0, t; }" : "=r"(a) : "l"(p)); return a;
}
#define SWZ(o) ((o) ^ (((o) >> 3) & 0x70))
__device__ __forceinline__ float sigmf(float x) { return 1.f / (1.f + __expf(-x)); }
__device__ __forceinline__ void split2(float x, bf16& h, bf16& l) {
    h = __float2bfloat16(x);
    l = __float2bfloat16(x - __bfloat162float(h));
}
__device__ __forceinline__ void ldm4(u32& r0, u32& r1, u32& r2, u32& r3, u32 a) {
    asm volatile("ldmatrix.sync.aligned.m8n8.x4.shared.b16 {%0,%1,%2,%3}, [%4];"
                 : "=r"(r0), "=r"(r1), "=r"(r2), "=r"(r3) : "r"(a));
}
__device__ __forceinline__ void mma16816(float* c, u32 a0, u32 a1, u32 a2, u32 a3, u32 b0, u32 b1) {
    asm volatile(
        "mma.sync.aligned.m16n8k16.row.col.f32.bf16.bf16.f32 "
        "{%0,%1,%2,%3}, {%4,%5,%6,%7}, {%8,%9}, {%0,%1,%2,%3};"
        : "+f"(c[0]), "+f"(c[1]), "+f"(c[2]), "+f"(c[3])
        : "r"(a0), "r"(a1), "r"(a2), "r"(a3), "r"(b0), "r"(b1));
}
__device__ __forceinline__ void cpa16(u32 dst, const void* src) {
    asm volatile("cp.async.cg.shared.global [%0], [%1], 16;" :: "r"(dst), "l"(src));
}
__device__ __forceinline__ void cpa_commit() {
    asm volatile("cp.async.commit_group;" ::: "memory");
}
__device__ __forceinline__ void cpa_wait0() {
    asm volatile("cp.async.wait_group 0;" ::: "memory");
}

// ---------------- grid barrier (128 CTAs co-resident on 148 SMs) ----------------
__device__ __forceinline__ void gridbar(unsigned* cnt, volatile unsigned* rel, unsigned& phase)
{
    __syncthreads();
    if (threadIdx.x == 0) {
        __threadfence();
        const unsigned target = phase + 1u;
        const unsigned v = atomicAdd(cnt, 1u);
        if (v == target * (unsigned)NCTAS - 1u) {
            __threadfence();
            *rel = target;
        } else {
            while (*rel < target) { __nanosleep(32); }
        }
    }
    __syncthreads();
    __threadfence();
    phase += 1u;
}

// ---------------- GEMM body: 128x64 tile, 256 thr, cp.async 2-stage -------------
__device__ __forceinline__ void gemm_body(
    char* As0, char* As1, char* Ws0, char* Ws1,
    const bf16* A1, int lda1, const bf16* W1, int ldw1, int nc1,
    const bf16* A2, int lda2, const bf16* W2, int ldw2, int nc2,
    int bm, int bn, float acc[2][4][4])
{
    const int tid = threadIdx.x;
    const int warp = tid >> 5, lane = tid & 31;
    const int wm = warp & 3, wn = warp >> 2;
    const int la_row = tid >> 1, la_kb = (tid & 1) * 64;
    const int lw_row = tid >> 2, lw_kb = (tid & 3) * 32;
    const int a_r = wm * 32 + (lane & 15), a_kb = (lane >> 4) * 16;
    const int b_r = wn * 32 + ((lane >> 4) << 3) + (lane & 7), b_kb = ((lane >> 3) & 1) * 16;
    const u32 sAb[2] = { s2u(As0), s2u(As1) };
    const u32 sWb[2] = { s2u(Ws0), s2u(Ws1) };
    // per-thread swizzled destination offsets (constant across chunks)
    u32 aoff[4], woff[2];
#pragma unroll
    for (int j = 0; j < 4; ++j) aoff[j] = SWZ((u32)(la_row * 128 + la_kb + j * 16));
#pragma unroll
    for (int j = 0; j < 2; ++j) woff[j] = SWZ((u32)(lw_row * 128 + lw_kb + j * 16));

    const int tot = nc1 + nc2;

    // issue chunk 0 -> buf 0
    {
        const bf16 *Ag, *Wg; int lda, ldw;
        if (0 < nc1) { Ag = A1; Wg = W1; lda = lda1; ldw = ldw1; }
        else         { Ag = A2; Wg = W2; lda = lda2; ldw = ldw2; }
        const bf16* ap = Ag + (size_t)(bm + la_row) * lda + la_kb / 2;
#pragma unroll
        for (int j = 0; j < 4; ++j) cpa16(sAb[0] + aoff[j], ap + j * 8);
        const bf16* wp = Wg + (size_t)(bn + lw_row) * ldw + lw_kb / 2;
#pragma unroll
        for (int j = 0; j < 2; ++j) cpa16(sWb[0] + woff[j], wp + j * 8);
        cpa_commit();
    }

    int buf = 0;
    for (int i = 0; i < tot; ++i) {
        cpa_wait0();
        __syncthreads();

        // issue next chunk into the other buffer (overlaps with compute below)
        if (i + 1 < tot) {
            const bf16 *Ag, *Wg; int lda, ldw, k0;
            if (i + 1 < nc1) { Ag = A1; Wg = W1; lda = lda1; ldw = ldw1; k0 = (i + 1) * 64; }
            else             { Ag = A2; Wg = W2; lda = lda2; ldw = ldw2; k0 = (i + 1 - nc1) * 64; }
            const int nb = buf ^ 1;
            const bf16* ap = Ag + (size_t)(bm + la_row) * lda + k0 + la_kb / 2;
#pragma unroll
            for (int j = 0; j < 4; ++j) cpa16(sAb[nb] + aoff[j], ap + j * 8);
            const bf16* wp = Wg + (size_t)(bn + lw_row) * ldw + k0 + lw_kb / 2;
#pragma unroll
            for (int j = 0; j < 2; ++j) cpa16(sWb[nb] + woff[j], wp + j * 8);
            cpa_commit();
        }

        const u32 sAc = sAb[buf];
        const u32 sWc = sWb[buf];

        // fragment-pipelined inner loop (ldsm for kk+1 before mmas of kk)
        u32 fa[2][8], fb[2][8];
        ldm4(fa[0][0], fa[0][1], fa[0][2], fa[0][3], sAc + SWZ(a_r * 128 + a_kb));
        ldm4(fa[0][4], fa[0][5], fa[0][6], fa[0][7], sAc + SWZ((a_r + 16) * 128 + a_kb));
        ldm4(fb[0][0], fb[0][1], fb[0][2], fb[0][3], sWc + SWZ(b_r * 128 + b_kb));
        ldm4(fb[0][4], fb[0][5], fb[0][6], fb[0][7], sWc + SWZ((b_r + 16) * 128 + b_kb));
#pragma unroll
        for (int kk = 0; kk < 4; ++kk) {
            const int cur = kk & 1, nxt = cur ^ 1;
            if (kk < 3) {
                const int kb = (kk + 1) * 32;
                ldm4(fa[nxt][0], fa[nxt][1], fa[nxt][2], fa[nxt][3], sAc + SWZ(a_r * 128 + kb + a_kb));
                ldm4(fa[nxt][4], fa[nxt][5], fa[nxt][6], fa[nxt][7], sAc + SWZ((a_r + 16) * 128 + kb + a_kb));
                ldm4(fb[nxt][0], fb[nxt][1], fb[nxt][2], fb[nxt][3], sWc + SWZ(b_r * 128 + kb + b_kb));
                ldm4(fb[nxt][4], fb[nxt][5], fb[nxt][6], fb[nxt][7], sWc + SWZ((b_r + 16) * 128 + kb + b_kb));
            }
            mma16816(acc[0][0], fa[cur][0], fa[cur][1], fa[cur][2], fa[cur][3], fb[cur][0], fb[cur][1]);
            mma16816(acc[0][1], fa[cur][0], fa[cur][1], fa[cur][2], fa[cur][3], fb[cur][2], fb[cur][3]);
            mma16816(acc[0][2], fa[cur][0], fa[cur][1], fa[cur][2], fa[cur][3], fb[cur][4], fb[cur][5]);
            mma16816(acc[0][3], fa[cur][0], fa[cur][1], fa[cur][2], fa[cur][3], fb[cur][6], fb[cur][7]);
            mma16816(acc[1][0], fa[cur][4], fa[cur][5], fa[cur][6], fa[cur][7], fb[cur][0], fb[cur][1]);
            mma16816(acc[1][1], fa[cur][4], fa[cur][5], fa[cur][6], fa[cur][7], fb[cur][2], fb[cur][3]);
            mma16816(acc[1][2], fa[cur][4], fa[cur][5], fa[cur][6], fa[cur][7], fb[cur][4], fb[cur][5]);
            mma16816(acc[1][3], fa[cur][4], fa[cur][5], fa[cur][6], fa[cur][7], fb[cur][6], fb[cur][7]);
        }
        buf ^= 1;
    }
    __syncthreads();   // protect smem before caller reuses (next step)
}

// ---------------- fused LSTM epilogue (with optional pre) -----------------------
__device__ __forceinline__ void lstm_epi(
    float acc[2][4][4], int bm, int bn,
    const float* bias, const float* pre,
    float* cst, bf16* hout, bf16* ysout)
{
    const int tid = threadIdx.x;
    const int warp = tid >> 5, lane = tid & 31;
    const int wm = warp & 3, wn = warp >> 2;
    const int rbase = bm + wm * 32 + (lane >> 2);
#pragma unroll
    for (int mt = 0; mt < 2; ++mt) {
#pragma unroll
        for (int nt = 0; nt < 4; ++nt) {
            float i1 = acc[mt][nt][0], f1 = acc[mt][nt][1];
            float i2 = acc[mt][nt][2], f2 = acc[mt][nt][3];
            const float gg1 = __shfl_xor_sync(0xffffffffu, i1, 1);
            const float oo1 = __shfl_xor_sync(0xffffffffu, f1, 1);
            const float gg2 = __shfl_xor_sync(0xffffffffu, i2, 1);
            const float oo2 = __shfl_xor_sync(0xffffffffu, f2, 1);
            if ((lane & 1) == 0) {
                const int col = bn + wn * 32 + nt * 8 + 2 * (lane & 3);
                const int jh = col >> 2;
                const float4 b4 = *(const float4*)&bias[col];
                const int r1 = rbase + mt * 16, r2 = r1 + 8;
                float gi1 = i1 + b4.x, gf1 = f1 + b4.y, gG1 = gg1 + b4.z, go1 = oo1 + b4.w;
                float gi2 = i2 + b4.x, gf2 = f2 + b4.y, gG2 = gg2 + b4.z, go2 = oo2 + b4.w;
                if (pre) {
                    const float4 p1 = *(const float4*)&pre[(size_t)r1 * G4 + col];
                    const float4 p2 = *(const float4*)&pre[(size_t)r2 * G4 + col];
                    gi1 += p1.x; gf1 += p1.y; gG1 += p1.z; go1 += p1.w;
                    gi2 += p2.x; gf2 += p2.y; gG2 += p2.z; go2 += p2.w;
                }
                {
                    const size_t ci = (size_t)r1 * H + jh;
                    const float cv = sigmf(gf1) * cst[ci] + sigmf(gi1) * tanhf(gG1);
                    const float hv = sigmf(go1) * tanhf(cv);
                    cst[ci] = cv;
                    bf16 hh, hl; split2(hv, hh, hl);
                    bf16* hr = hout + (size_t)r1 * K3H;
                    hr[jh] = hh; hr[H + jh] = hh; hr[2 * H + jh] = hl;
                    if (ysout) { bf16* yr = ysout + (size_t)r1 * K3H; yr[jh] = hh; yr[H + jh] = hh; yr[2 * H + jh] = hl; }
                }
                {
                    const size_t ci = (size_t)r2 * H + jh;
                    const float cv = sigmf(gf2) * cst[ci] + sigmf(gi2) * tanhf(gG2);
                    const float hv = sigmf(go2) * tanhf(cv);
                    cst[ci] = cv;
                    bf16 hh, hl; split2(hv, hh, hl);
                    bf16* hr = hout + (size_t)r2 * K3H;
                    hr[jh] = hh; hr[H + jh] = hh; hr[2 * H + jh] = hl;
                    if (ysout) { bf16* yr = ysout + (size_t)r2 * K3H; yr[jh] = hh; yr[H + jh] = hh; yr[2 * H + jh] = hl; }
                }
            }
        }
    }
}

// ---------------- batched GEMM (EPI=0 plain fp32 out, EPI=2 fc scatter) ---------
template<int EPI>
__global__ __launch_bounds__(256)
void hgemm(const bf16* __restrict__ A1, int lda1,
           const bf16* __restrict__ W1, int ldw1, int nc1,
           const float* __restrict__ bias,
           float* __restrict__ Cout, int ldc)
{
    __shared__ bf16 As[2][128*64];
    __shared__ bf16 Ws[2][64*64];
    const int bm = blockIdx.y * 128, bn = blockIdx.x * 64;
    float acc[2][4][4];
#pragma unroll
    for (int m = 0; m < 2; ++m)
#pragma unroll
        for (int n = 0; n < 4; ++n)
#pragma unroll
            for (int q = 0; q < 4; ++q) acc[m][n][q] = 0.f;

    gemm_body((char*)As[0], (char*)As[1], (char*)Ws[0], (char*)Ws[1],
              A1, lda1, W1, ldw1, nc1,
              (const bf16*)0, 0, (const bf16*)0, 0, 0, bm, bn, acc);

    const int tid = threadIdx.x;
    const int warp = tid >> 5, lane = tid & 31;
    const int wm = warp & 3, wn = warp >> 2;
    const int rbase = bm + wm * 32 + (lane >> 2);

    if (EPI == 0) {
#pragma unroll
        for (int mt = 0; mt < 2; ++mt) {
#pragma unroll
            for (int nt = 0; nt < 4; ++nt) {
                const int col = bn + wn * 32 + nt * 8 + 2 * (lane & 3);
                const int r1 = rbase + mt * 16, r2 = r1 + 8;
                *(float2*)&Cout[(size_t)r1 * ldc + col] = make_float2(acc[mt][nt][0], acc[mt][nt][1]);
                *(float2*)&Cout[(size_t)r2 * ldc + col] = make_float2(acc[mt][nt][2], acc[mt][nt][3]);
            }
        }
    } else {
#pragma unroll
        for (int mt = 0; mt < 2; ++mt) {
#pragma unroll
            for (int nt = 0; nt < 4; ++nt) {
                const int col = bn + wn * 32 + nt * 8 + 2 * (lane & 3);
                const int r1 = rbase + mt * 16, r2 = r1 + 8;
                {
                    const int bb = r1 & (Bn - 1), tt = r1 >> 9;
                    float* o = Cout + (size_t)bb * (Pn * CCn) + (size_t)tt * CCn;
                    if (col < CCn)     o[col]     = acc[mt][nt][0] + bias[col];
                    if (col + 1 < CCn) o[col + 1] = acc[mt][nt][1] + bias[col + 1];
                }
                {
                    const int bb = r2 & (Bn - 1), tt = r2 >> 9;
                    float* o = Cout + (size_t)bb * (Pn * CCn) + (size_t)tt * CCn;
                    if (col < CCn)     o[col]     = acc[mt][nt][2] + bias[col];
                    if (col + 1 < CCn) o[col + 1] = acc[mt][nt][3] + bias[col + 1];
                }
            }
        }
    }
}

// ---------------- persistent encoder-layer recurrence ---------------------------
__global__ __launch_bounds__(256)
void enc_seq(bf16* hA, bf16* hBp, const bf16* __restrict__ W,
             const float* __restrict__ bias, const float* __restrict__ preBase,
             float* __restrict__ cst, bf16* __restrict__ ysBase, int steps,
             unsigned* barCnt, unsigned* barRel)
{
    __shared__ bf16 As[2][128*64];
    __shared__ bf16 Ws[2][64*64];
    const int bm = blockIdx.y * 128, bn = blockIdx.x * 64;
    bf16* hc = hA; bf16* hn = hBp;
    unsigned phase = 0;
    for (int t = 0; t < steps; ++t) {
        float acc[2][4][4];
#pragma unroll
        for (int m = 0; m < 2; ++m)
#pragma unroll
            for (int n = 0; n < 4; ++n)
#pragma unroll
                for (int q = 0; q < 4; ++q) acc[m][n][q] = 0.f;
        gemm_body((char*)As[0], (char*)As[1], (char*)Ws[0], (char*)Ws[1],
                  hc, K3H, W, K3H, K3H / 64,
                  (const bf16*)0, 0, (const bf16*)0, 0, 0, bm, bn, acc);
        lstm_epi(acc, bm, bn, bias, preBase + (size_t)t * Bn * G4, cst, hn,
                 ysBase ? (ysBase + (size_t)t * Bn * K3H) : (bf16*)0);
        gridbar(barCnt, (volatile unsigned*)barRel, phase);
        bf16* tmp = hc; hc = hn; hn = tmp;
    }
}

// ---------------- persistent decoder recurrence ---------------------------------
__global__ __launch_bounds__(256)
void dec_seq(bf16* h0A, bf16* h0B, bf16* h1A, bf16* h1B,
             const bf16* __restrict__ i03,
             const bf16* __restrict__ dWih0, const bf16* __restrict__ Wfold,
             const bf16* __restrict__ dWhh0, const bf16* __restrict__ dWih1,
             const bf16* __restrict__ dWhh1,
             const float* __restrict__ dB0, const float* __restrict__ dB0f,
             const float* __restrict__ dB1,
             float* __restrict__ c0, float* __restrict__ c1,
             bf16* __restrict__ ysBase, int steps,
             unsigned* barCnt, unsigned* barRel)
{
    __shared__ bf16 As[2][128*64];
    __shared__ bf16 Ws[2][64*64];
    const int bm = blockIdx.y * 128, bn = blockIdx.x * 64;
    bf16 *h0c = h0A, *h0n = h0B, *h1c = h1A, *h1n = h1B;
    unsigned phase = 0;
    for (int t = 0; t < steps; ++t) {
        {
            float acc[2][4][4];
#pragma unroll
            for (int m = 0; m < 2; ++m)
#pragma unroll
                for (int n = 0; n < 4; ++n)
#pragma unroll
                    for (int q = 0; q < 4; ++q) acc[m][n][q] = 0.f;
            if (t == 0) {
                gemm_body((char*)As[0], (char*)As[1], (char*)Ws[0], (char*)Ws[1],
                          i03, K3E, dWih0, K3E, K3E / 64,
                          h0c, K3H, dWhh0, K3H, K3H / 64, bm, bn, acc);
                lstm_epi(acc, bm, bn, dB0, (const float*)0, c0, h0n, (bf16*)0);
            } else {
                gemm_body((char*)As[0], (char*)As[1], (char*)Ws[0], (char*)Ws[1],
                          h1c, K3H, Wfold, K3H, K3H / 64,
                          h0c, K3H, dWhh0, K3H, K3H / 64, bm, bn, acc);
                lstm_epi(acc, bm, bn, dB0f, (const float*)0, c0, h0n, (bf16*)0);
            }
            gridbar(barCnt, (volatile unsigned*)barRel, phase);
            bf16* tmp = h0c; h0c = h0n; h0n = tmp;
        }
        {
            float acc[2][4][4];
#pragma unroll
            for (int m = 0; m < 2; ++m)
#pragma unroll
                for (int n = 0; n < 4; ++n)
#pragma unroll
                    for (int q = 0; q < 4; ++q) acc[m][n][q] = 0.f;
            gemm_body((char*)As[0], (char*)As[1], (char*)Ws[0], (char*)Ws[1],
                      h0c, K3H, dWih1, K3H, K3H / 64,
                      h1c, K3H, dWhh1, K3H, K3H / 64, bm, bn, acc);
            lstm_epi(acc, bm, bn, dB1, (const float*)0, c1, h1n,
                     ysBase + (size_t)t * Bn * K3H);
            gridbar(barCnt, (volatile unsigned*)barRel, phase);
            bf16* tmp = h1c; h1c = h1n; h1n = tmp;
        }
    }
}

// ---------------- setup kernels ---------------------------------------------------
__global__ void k_w3(const float* __restrict__ src, bf16* __restrict__ dst, int K, int Kp)
{
    size_t idx = (size_t)blockIdx.x * blockDim.x + threadIdx.x;
    if (idx >= (size_t)G4 * Kp) return;
    int np = (int)(idx / Kp), k = (int)(idx % Kp);
    int j = np >> 2, g = np & 3;
    float v = (k < K) ? src[((size_t)(g * H + j)) * K + k] : 0.f;
    bf16 h, l; split2(v, h, l);
    bf16* d = dst + (size_t)np * 3 * Kp;
    d[k] = h; d[Kp + k] = l; d[2 * Kp + k] = h;
}
__global__ void k_a3w(const float* __restrict__ src, bf16* __restrict__ dst, int K, int Kp)
{
    size_t idx = (size_t)blockIdx.x * blockDim.x + threadIdx.x;
    if (idx >= (size_t)G4 * Kp) return;
    int np = (int)(idx / Kp), k = (int)(idx % Kp);
    int j = np >> 2, g = np & 3;
    float v = (k < K) ? src[((size_t)(g * H + j)) * K + k] : 0.f;
    bf16 h, l; split2(v, h, l);
    bf16* d = dst + (size_t)np * 3 * Kp;
    d[k] = h; d[Kp + k] = h; d[2 * Kp + k] = l;
}
__global__ void k_fcwt3(const float* __restrict__ fcW, bf16* __restrict__ dst)
{
    int idx = blockIdx.x * blockDim.x + threadIdx.x;
    if (idx >= H * EPB) return;
    int hrow = idx / EPB, c = idx % EPB;
    float v = (c < CCn) ? fcW[(size_t)c * H + hrow] : 0.f;
    bf16 h, l; split2(v, h, l);
    bf16* d = dst + (size_t)hrow * K3E;
    d[c] = h; d[EPB + c] = l; d[2 * EPB + c] = h;
}
__global__ void k_fcw3(const float* __restrict__ fcW, bf16* __restrict__ dst)
{
    int idx = blockIdx.x * blockDim.x + threadIdx.x;
    if (idx >= NCP * H) return;
    int n = idx / H, hcol = idx % H;
    float v = (n < CCn) ? fcW[(size_t)n * H + hcol] : 0.f;
    bf16 h, l; split2(v, h, l);
    bf16* d = dst + (size_t)n * K3H;
    d[hcol] = h; d[H + hcol] = l; d[2 * H + hcol] = h;
}
__global__ void k_split3w(const float* __restrict__ src, bf16* __restrict__ dst)
{
    size_t idx = (size_t)blockIdx.x * blockDim.x + threadIdx.x;
    if (idx >= (size_t)G4 * H) return;
    int np = (int)(idx / H), k = (int)(idx % H);
    bf16 h, l; split2(src[idx], h, l);
    bf16* d = dst + (size_t)np * K3H;
    d[k] = h; d[H + k] = l; d[2 * H + k] = h;
}
__global__ void k_x3(const float* __restrict__ x, bf16* __restrict__ dst)
{
    size_t idx = (size_t)blockIdx.x * blockDim.x + threadIdx.x;
    if (idx >= (size_t)TB * EPB) return;
    int e = (int)(idx % EPB);
    int b = (int)((idx / EPB) % Bn);
    int t = (int)(idx / ((size_t)EPB * Bn));
    float v = (e < E) ? x[(size_t)b * Tn * E + (size_t)t * E + e] : 0.f;
    bf16 h, l; split2(v, h, l);
    bf16* d = dst + ((size_t)t * Bn + b) * K3E;
    d[e] = h; d[EPB + e] = h; d[2 * EPB + e] = l;
}
__global__ void k_i03(const float* __restrict__ x, bf16* __restrict__ dst)
{
    int i = blockIdx.x * blockDim.x + threadIdx.x;
    if (i >= Bn * EPB) return;
    int b = i / EPB, e = i % EPB;
    float v = (e < E) ? x[(size_t)b * Tn * E + (size_t)(Tn - 1) * E + e] : 0.f;
    bf16 h, l; split2(v, h, l);
    bf16* d = dst + (size_t)b * K3E;
    d[e] = h; d[EPB + e] = h; d[2 * EPB + e] = l;
}
__global__ void k_bias(const float* __restrict__ a, const float* __restrict__ b, float* __restrict__ d)
{
    int n = blockIdx.x * blockDim.x + threadIdx.x;
    if (n >= G4) return;
    int j = n >> 2, g = n & 3;
    d[n] = a[g * H + j] + b[g * H + j];
}
__global__ void k_foldbias(const float* __restrict__ dWih0, const float* __restrict__ fcb,
                           const float* __restrict__ dB0, float* __restrict__ out)
{
    int n = blockIdx.x * blockDim.x + threadIdx.x;
    if (n >= G4) return;
    int j = n >> 2, g = n & 3;
    float s = dB0[n];
    const float* row = dWih0 + (size_t)(g * H + j) * E;
    for (int c = 0; c < CCn; ++c) s += row[c] * fcb[c];
    out[n] = s;
}
__global__ void k_fcb(const float* __restrict__ fcb, float* __restrict__ d)
{
    int n = blockIdx.x * blockDim.x + threadIdx.x;
    if (n >= NCP) return;
    d[n] = (n < CCn) ? fcb[n] : 0.f;
}
__global__ void k_zf(float* p, int n) { int i = blockIdx.x * blockDim.x + threadIdx.x; if (i < n) p[i] = 0.f; }
__global__ void k_zb(bf16* p, size_t n) { size_t i = (size_t)blockIdx.x * blockDim.x + threadIdx.x; if (i < n) ((unsigned short*)p)[i] = 0; }
__global__ void k_zu(unsigned* p) { if (threadIdx.x < 8) p[threadIdx.x] = 0u; }

// ---------------- entry ----------------------------------------------------------
extern "C" void kernel_launch(void* const* d_in, const int* in_sizes, int n_in,
                              void* d_out, int out_size)
{
    const float* x_enc  = (const float*)d_in[0];
    const float* e_Wih0 = (const float*)d_in[4],  *e_Whh0 = (const float*)d_in[5];
    const float* e_bih0 = (const float*)d_in[6],  *e_bhh0 = (const float*)d_in[7];
    const float* e_Wih1 = (const float*)d_in[8],  *e_Whh1 = (const float*)d_in[9];
    const float* e_bih1 = (const float*)d_in[10], *e_bhh1 = (const float*)d_in[11];
    const float* d_Wih0 = (const float*)d_in[12], *d_Whh0 = (const float*)d_in[13];
    const float* d_bih0 = (const float*)d_in[14], *d_bhh0 = (const float*)d_in[15];
    const float* d_Wih1 = (const float*)d_in[16], *d_Whh1 = (const float*)d_in[17];
    const float* d_bih1 = (const float*)d_in[18], *d_bhh1 = (const float*)d_in[19];
    const float* fc_W   = (const float*)d_in[20], *fc_b   = (const float*)d_in[21];
    float* out = (float*)d_out;

    bf16 *eWih0, *dWih0, *eWhh0, *eWih1, *eWhh1, *dWhh0, *dWih1, *dWhh1;
    bf16 *Wfold, *fcW3, *fcwt, *dwA, *x3, *ys3, *hB, *i03;
    float *pre, *cbuf, *bias;
    unsigned* bar;
    cudaGetSymbolAddress((void**)&eWih0, g_eWih0); cudaGetSymbolAddress((void**)&dWih0, g_dWih0);
    cudaGetSymbolAddress((void**)&eWhh0, g_eWhh0); cudaGetSymbolAddress((void**)&eWih1, g_eWih1);
    cudaGetSymbolAddress((void**)&eWhh1, g_eWhh1); cudaGetSymbolAddress((void**)&dWhh0, g_dWhh0);
    cudaGetSymbolAddress((void**)&dWih1, g_dWih1); cudaGetSymbolAddress((void**)&dWhh1, g_dWhh1);
    cudaGetSymbolAddress((void**)&Wfold, g_Wfold); cudaGetSymbolAddress((void**)&fcW3,  g_fcW);
    cudaGetSymbolAddress((void**)&fcwt,  g_fcwt);  cudaGetSymbolAddress((void**)&dwA,   g_dwA);
    cudaGetSymbolAddress((void**)&x3,    g_x3);    cudaGetSymbolAddress((void**)&ys3,   g_ys3);
    cudaGetSymbolAddress((void**)&hB,    g_h);     cudaGetSymbolAddress((void**)&i03,   g_i03);
    cudaGetSymbolAddress((void**)&pre,   g_pre);   cudaGetSymbolAddress((void**)&cbuf,  g_c);
    cudaGetSymbolAddress((void**)&bias,  g_bias);  cudaGetSymbolAddress((void**)&bar,   g_bar);

    float* eB0  = bias;          float* eB1 = bias + G4;
    float* dB0  = bias + 2 * G4; float* dB1 = bias + 3 * G4;
    float* dB0f = bias + 4 * G4; float* fcb = bias + 5 * G4;
    const size_t HP = (size_t)Bn * K3H;
    bf16* h0A = hB;          bf16* h0B = hB + HP;
    bf16* h1A = hB + 2 * HP; bf16* h1B = hB + 3 * HP;
    float* c0 = cbuf; float* c1 = cbuf + (size_t)Bn * H;
    const int thr = 256;
    const size_t BHK = (size_t)Bn * K3H;

    // ---- setup ----
    {
        size_t nE = (size_t)G4 * EPB, nH = (size_t)G4 * H;
        k_w3<<<(unsigned)((nE + thr - 1) / thr), thr>>>(e_Wih0, eWih0, E, EPB);
        k_w3<<<(unsigned)((nE + thr - 1) / thr), thr>>>(d_Wih0, dWih0, E, EPB);
        k_w3<<<(unsigned)((nH + thr - 1) / thr), thr>>>(e_Whh0, eWhh0, H, H);
        k_w3<<<(unsigned)((nH + thr - 1) / thr), thr>>>(e_Wih1, eWih1, H, H);
        k_w3<<<(unsigned)((nH + thr - 1) / thr), thr>>>(e_Whh1, eWhh1, H, H);
        k_w3<<<(unsigned)((nH + thr - 1) / thr), thr>>>(d_Whh0, dWhh0, H, H);
        k_w3<<<(unsigned)((nH + thr - 1) / thr), thr>>>(d_Wih1, dWih1, H, H);
        k_w3<<<(unsigned)((nH + thr - 1) / thr), thr>>>(d_Whh1, dWhh1, H, H);
        k_a3w<<<(unsigned)((nE + thr - 1) / thr), thr>>>(d_Wih0, dwA, E, EPB);
        k_fcwt3<<<(H * EPB + thr - 1) / thr, thr>>>(fc_W, fcwt);
        k_fcw3<<<(NCP * H + thr - 1) / thr, thr>>>(fc_W, fcW3);
        k_bias<<<(G4 + thr - 1) / thr, thr>>>(e_bih0, e_bhh0, eB0);
        k_bias<<<(G4 + thr - 1) / thr, thr>>>(e_bih1, e_bhh1, eB1);
        k_bias<<<(G4 + thr - 1) / thr, thr>>>(d_bih0, d_bhh0, dB0);
        k_bias<<<(G4 + thr - 1) / thr, thr>>>(d_bih1, d_bhh1, dB1);
        k_foldbias<<<(G4 + thr - 1) / thr, thr>>>(d_Wih0, fc_b, dB0, dB0f);
        k_fcb<<<(NCP + thr - 1) / thr, thr>>>(fc_b, fcb);
        k_zu<<<1, 32>>>(bar);
    }
    // Wfold = dWih0' @ fcW^T (fp32) then split3 W-style
    {
        dim3 g(H / 64, G4 / 128);
        hgemm<0><<<g, 256>>>(dwA, K3E, fcwt, K3E, K3E / 64, (const float*)0, pre, H);
        size_t n = (size_t)G4 * H;
        k_split3w<<<(unsigned)((n + thr - 1) / thr), thr>>>(pre, Wfold);
    }
    // ---- states + inputs ----
    k_zf<<<(2 * Bn * H + thr - 1) / thr, thr>>>(cbuf, 2 * Bn * H);
    k_zb<<<(unsigned)((4 * BHK + thr - 1) / thr), thr>>>(hB, 4 * BHK);
    {
        size_t n = (size_t)TB * EPB;
        k_x3<<<(unsigned)((n + thr - 1) / thr), thr>>>(x_enc, x3);
    }
    k_i03<<<(Bn * EPB + thr - 1) / thr, thr>>>(x_enc, i03);

    // ---- encoder L0: batched input GEMM, then persistent recurrence ----
    {
        dim3 g(G4 / 64, TB / 128);
        hgemm<0><<<g, 256>>>(x3, K3E, eWih0, K3E, K3E / 64, (const float*)0, pre, G4);
    }
    {
        dim3 g(G4 / 64, Bn / 128);  // 32 x 4 = 128 CTAs
        enc_seq<<<g, 256>>>(h0A, h0B, eWhh0, eB0, pre, c0, ys3, Tn, bar + 0, bar + 1);
    }
    // ---- encoder L1 ----
    {
        dim3 g(G4 / 64, TB / 128);
        hgemm<0><<<g, 256>>>(ys3, K3H, eWih1, K3H, K3H / 64, (const float*)0, pre, G4);
    }
    {
        dim3 g(G4 / 64, Bn / 128);
        enc_seq<<<g, 256>>>(h1A, h1B, eWhh1, eB1, pre, c1, (bf16*)0, Tn, bar + 2, bar + 3);
    }
    // ---- decoder (persistent, fc folded) ----
    {
        dim3 g(G4 / 64, Bn / 128);
        dec_seq<<<g, 256>>>(h0A, h0B, h1A, h1B, i03,
                            dWih0, Wfold, dWhh0, dWih1, dWhh1,
                            dB0, dB0f, dB1, c0, c1, ys3, Pn, bar + 4, bar + 5);
    }
    // ---- batched final fc ----
    {
        dim3 g(NCP / 64, TB / 128);
        hgemm<2><<<g, 256>>>(ys3, K3H, fcW3, K3H, K3H / 64, fcb, out, 0);
    }
}